// round 1
// baseline (speedup 1.0000x reference)
#include <cuda_runtime.h>

#define D      128
#define DM     1024
#define BATCH  4
#define SEQ    4096
#define ROWS   (BATCH * SEQ)   // 16384
#define SPLITS 32
#define PAD    4

// Scratch (allocation-free rule: __device__ globals)
__device__ float g_q[ROWS * D];
__device__ float g_k[ROWS * D];
__device__ float g_v[ROWS * D];
__device__ float g_mpart[BATCH * SPLITS * D * D];
__device__ float g_m[BATCH * D * D];

// ---------------------------------------------------------------------------
// Kernel 1: QKV projection. C[row, d] = sum_m x[row, m] * W[d, m] + b[d]
// Both x and W are K-major (m contiguous): "NT" layout. 128x128x32 tile,
// 256 threads, 8x8 micro-tile per thread. blockIdx.y selects q/k/v.
// ---------------------------------------------------------------------------
__global__ __launch_bounds__(256, 2) void qkv_kernel(
    const float* __restrict__ x,
    const float* __restrict__ Wq, const float* __restrict__ bq,
    const float* __restrict__ Wk, const float* __restrict__ bk,
    const float* __restrict__ Wv, const float* __restrict__ bv)
{
    const float* W;
    const float* bias;
    float* out;
    if (blockIdx.y == 0)      { W = Wq; bias = bq; out = g_q; }
    else if (blockIdx.y == 1) { W = Wk; bias = bk; out = g_k; }
    else                      { W = Wv; bias = bv; out = g_v; }

    __shared__ float As[32][128 + PAD];   // transposed: As[k][row]
    __shared__ float Bs[32][128 + PAD];   // transposed: Bs[k][d]

    const int tid = threadIdx.x;
    const int tx  = tid & 15;        // 0..15 -> output cols tx*8..tx*8+7
    const int ty  = tid >> 4;        // 0..15 -> output rows ty*8..ty*8+7
    const int row0 = blockIdx.x * 128;

    float acc[8][8];
    #pragma unroll
    for (int i = 0; i < 8; i++)
        #pragma unroll
        for (int j = 0; j < 8; j++) acc[i][j] = 0.0f;

    for (int kt = 0; kt < DM; kt += 32) {
        // Load 128x32 A tile (x) and 128x32 B tile (W), both K-contiguous.
        #pragma unroll
        for (int i = 0; i < 4; i++) {
            int slot = tid + i * 256;      // 1024 float4 slots: 128 rows x 8 cols
            int r  = slot >> 3;
            int c4 = (slot & 7) * 4;
            float4 va = *(const float4*)&x[(size_t)(row0 + r) * DM + kt + c4];
            As[c4 + 0][r] = va.x; As[c4 + 1][r] = va.y;
            As[c4 + 2][r] = va.z; As[c4 + 3][r] = va.w;
            float4 vb = *(const float4*)&W[(size_t)r * DM + kt + c4];
            Bs[c4 + 0][r] = vb.x; Bs[c4 + 1][r] = vb.y;
            Bs[c4 + 2][r] = vb.z; Bs[c4 + 3][r] = vb.w;
        }
        __syncthreads();

        #pragma unroll
        for (int kk = 0; kk < 32; kk++) {
            float ra[8], rb[8];
            *(float4*)&ra[0] = *(float4*)&As[kk][ty * 8];
            *(float4*)&ra[4] = *(float4*)&As[kk][ty * 8 + 4];
            *(float4*)&rb[0] = *(float4*)&Bs[kk][tx * 8];
            *(float4*)&rb[4] = *(float4*)&Bs[kk][tx * 8 + 4];
            #pragma unroll
            for (int i = 0; i < 8; i++)
                #pragma unroll
                for (int j = 0; j < 8; j++)
                    acc[i][j] += ra[i] * rb[j];
        }
        __syncthreads();
    }

    // Epilogue: add bias, store.
    #pragma unroll
    for (int i = 0; i < 8; i++) {
        int r = row0 + ty * 8 + i;
        #pragma unroll
        for (int jv = 0; jv < 2; jv++) {
            int c = tx * 8 + jv * 4;
            float4 o;
            o.x = acc[i][jv * 4 + 0] + bias[c + 0];
            o.y = acc[i][jv * 4 + 1] + bias[c + 1];
            o.z = acc[i][jv * 4 + 2] + bias[c + 2];
            o.w = acc[i][jv * 4 + 3] + bias[c + 3];
            *(float4*)&out[(size_t)r * D + c] = o;
        }
    }
}

// ---------------------------------------------------------------------------
// Kernel 2a: split-K partials of M_b = K_b^T V_b  ([128,128] per batch).
// Each CTA handles 128 t-rows (SEQ/SPLITS) of one batch. "TN" layout: both
// operands are [t, d] with d contiguous -> tiles load directly, no transpose.
// ---------------------------------------------------------------------------
__global__ __launch_bounds__(256) void ktv_partial_kernel()
{
    const int b     = blockIdx.y;
    const int split = blockIdx.x;
    const int t0    = split * (SEQ / SPLITS);   // 128 rows of t

    const float* kb = g_k + (size_t)b * SEQ * D;
    const float* vb = g_v + (size_t)b * SEQ * D;

    __shared__ float Ks[16][D];
    __shared__ float Vs[16][D];

    const int tid = threadIdx.x;
    const int tx  = tid & 15;
    const int ty  = tid >> 4;

    float acc[8][8];
    #pragma unroll
    for (int i = 0; i < 8; i++)
        #pragma unroll
        for (int j = 0; j < 8; j++) acc[i][j] = 0.0f;

    for (int tt = 0; tt < SEQ / SPLITS; tt += 16) {
        #pragma unroll
        for (int i = 0; i < 2; i++) {
            int slot = tid + i * 256;        // 512 float4 slots: 16 rows x 32 cols
            int r  = slot >> 5;
            int c4 = (slot & 31) * 4;
            *(float4*)&Ks[r][c4] = *(const float4*)&kb[(size_t)(t0 + tt + r) * D + c4];
            *(float4*)&Vs[r][c4] = *(const float4*)&vb[(size_t)(t0 + tt + r) * D + c4];
        }
        __syncthreads();

        #pragma unroll
        for (int kk = 0; kk < 16; kk++) {
            float ra[8], rb[8];
            *(float4*)&ra[0] = *(float4*)&Ks[kk][ty * 8];
            *(float4*)&ra[4] = *(float4*)&Ks[kk][ty * 8 + 4];
            *(float4*)&rb[0] = *(float4*)&Vs[kk][tx * 8];
            *(float4*)&rb[4] = *(float4*)&Vs[kk][tx * 8 + 4];
            #pragma unroll
            for (int i = 0; i < 8; i++)
                #pragma unroll
                for (int j = 0; j < 8; j++)
                    acc[i][j] += ra[i] * rb[j];
        }
        __syncthreads();
    }

    float* outp = g_mpart + ((size_t)(b * SPLITS + split)) * D * D;
    #pragma unroll
    for (int i = 0; i < 8; i++) {
        int r = ty * 8 + i;
        #pragma unroll
        for (int jv = 0; jv < 2; jv++) {
            int c = tx * 8 + jv * 4;
            *(float4*)&outp[(size_t)r * D + c] = *(float4*)&acc[i][jv * 4];
        }
    }
}

// ---------------------------------------------------------------------------
// Kernel 2b: reduce the 32 split partials into g_m.
// ---------------------------------------------------------------------------
__global__ __launch_bounds__(256) void reduce_m_kernel()
{
    int idx = blockIdx.x * 256 + threadIdx.x;    // 0 .. BATCH*D*D-1 (65536)
    int b   = idx >> 14;
    int ij  = idx & 16383;
    float s = 0.0f;
    #pragma unroll
    for (int p = 0; p < SPLITS; p++)
        s += g_mpart[(((size_t)(b * SPLITS + p)) << 14) + ij];
    g_m[idx] = s;
}

// ---------------------------------------------------------------------------
// Kernel 3: out[b,s,:] = scale * q[b,s,:] @ M_b.  NN GEMM, K=128.
// ---------------------------------------------------------------------------
__global__ __launch_bounds__(256, 2) void out_kernel(float* __restrict__ out)
{
    const int b  = blockIdx.y;
    const int s0 = blockIdx.x * 128;

    const float* q = g_q + (size_t)b * SEQ * D;
    const float* M = g_m + (size_t)b * D * D;

    __shared__ float As[32][128 + PAD];   // transposed q tile: As[k][s]
    __shared__ float Bs[32][128 + PAD];   // natural M tile: Bs[k][n]

    const int tid = threadIdx.x;
    const int tx  = tid & 15;
    const int ty  = tid >> 4;

    float acc[8][8];
    #pragma unroll
    for (int i = 0; i < 8; i++)
        #pragma unroll
        for (int j = 0; j < 8; j++) acc[i][j] = 0.0f;

    for (int kt = 0; kt < D; kt += 32) {
        // A tile: q[s0+r][kt+c] -> transposed store
        #pragma unroll
        for (int i = 0; i < 4; i++) {
            int slot = tid + i * 256;      // 1024 slots: 128 rows x 8 cols
            int r  = slot >> 3;
            int c4 = (slot & 7) * 4;
            float4 va = *(const float4*)&q[(size_t)(s0 + r) * D + kt + c4];
            As[c4 + 0][r] = va.x; As[c4 + 1][r] = va.y;
            As[c4 + 2][r] = va.z; As[c4 + 3][r] = va.w;
        }
        // B tile: M[kt+dr][c], already [K][N] -> direct store
        #pragma unroll
        for (int i = 0; i < 4; i++) {
            int slot = tid + i * 256;      // 1024 slots: 32 rows x 32 cols
            int dr = slot >> 5;
            int c4 = (slot & 31) * 4;
            *(float4*)&Bs[dr][c4] = *(const float4*)&M[(size_t)(kt + dr) * D + c4];
        }
        __syncthreads();

        #pragma unroll
        for (int kk = 0; kk < 32; kk++) {
            float ra[8], rb[8];
            *(float4*)&ra[0] = *(float4*)&As[kk][ty * 8];
            *(float4*)&ra[4] = *(float4*)&As[kk][ty * 8 + 4];
            *(float4*)&rb[0] = *(float4*)&Bs[kk][tx * 8];
            *(float4*)&rb[4] = *(float4*)&Bs[kk][tx * 8 + 4];
            #pragma unroll
            for (int i = 0; i < 8; i++)
                #pragma unroll
                for (int j = 0; j < 8; j++)
                    acc[i][j] += ra[i] * rb[j];
        }
        __syncthreads();
    }

    const float scale = 0.08838834764831845f;   // 128^-0.5
    #pragma unroll
    for (int i = 0; i < 8; i++) {
        int s = s0 + ty * 8 + i;
        #pragma unroll
        for (int jv = 0; jv < 2; jv++) {
            int c = tx * 8 + jv * 4;
            float4 o;
            o.x = acc[i][jv * 4 + 0] * scale;
            o.y = acc[i][jv * 4 + 1] * scale;
            o.z = acc[i][jv * 4 + 2] * scale;
            o.w = acc[i][jv * 4 + 3] * scale;
            *(float4*)&out[((size_t)b * SEQ + s) * D + c] = o;
        }
    }
}

// ---------------------------------------------------------------------------
extern "C" void kernel_launch(void* const* d_in, const int* in_sizes, int n_in,
                              void* d_out, int out_size)
{
    const float* x  = (const float*)d_in[0];
    const float* Wq = (const float*)d_in[1];
    const float* bq = (const float*)d_in[2];
    const float* Wk = (const float*)d_in[3];
    const float* bk = (const float*)d_in[4];
    const float* Wv = (const float*)d_in[5];
    const float* bv = (const float*)d_in[6];
    float* out = (float*)d_out;

    qkv_kernel<<<dim3(ROWS / 128, 3), 256>>>(x, Wq, bq, Wk, bk, Wv, bv);
    ktv_partial_kernel<<<dim3(SPLITS, BATCH), 256>>>();
    reduce_m_kernel<<<dim3(BATCH * D * D / 256), 256>>>();
    out_kernel<<<dim3(SEQ / 128, BATCH), 256>>>(out);
}

// round 3
// speedup vs baseline: 1.7444x; 1.7444x over previous
#include <cuda_runtime.h>
#include <cuda_bf16.h>
#include <cstdint>

#define D      128
#define DM     1024
#define BATCH  4
#define SEQ    4096
#define ROWS   (BATCH * SEQ)   // 16384
#define SPLITS 32
#define PAD    4
#define NCH    (DM / 32)       // 32 k-chunks of 32

// Scratch (allocation-free rule: __device__ globals)
__device__ float g_q[ROWS * D];
__device__ float g_k[ROWS * D];
__device__ float g_v[ROWS * D];
__device__ float g_mpart[BATCH * SPLITS * D * D];
__device__ float g_m[BATCH * D * D];
__device__ __nv_bfloat16 g_xh[(size_t)ROWS * DM];
__device__ __nv_bfloat16 g_xl[(size_t)ROWS * DM];
__device__ __nv_bfloat16 g_wh[3 * D * DM];
__device__ __nv_bfloat16 g_wl[3 * D * DM];

// ===========================================================================
// helpers (sm_80-era PTX only: ldmatrix / mma.sync / cp.async)
// ===========================================================================
__device__ __forceinline__ uint32_t s2u(const void* p) {
    uint32_t a;
    asm("{ .reg .u64 t; cvta.to.shared.u64 t, %1; cvt.u32.u64 %0, t; }"
        : "=r"(a) : "l"(p));
    return a;
}
__device__ __forceinline__ void ldsm4(uint32_t* r, uint32_t addr) {
    asm volatile("ldmatrix.sync.aligned.m8n8.x4.shared.b16 {%0,%1,%2,%3}, [%4];"
                 : "=r"(r[0]), "=r"(r[1]), "=r"(r[2]), "=r"(r[3]) : "r"(addr));
}
__device__ __forceinline__ void mma_bf16(float* d, const uint32_t* a,
                                         uint32_t b0, uint32_t b1) {
    asm volatile(
        "mma.sync.aligned.m16n8k16.row.col.f32.bf16.bf16.f32 "
        "{%0,%1,%2,%3}, {%4,%5,%6,%7}, {%8,%9}, {%0,%1,%2,%3};"
        : "+f"(d[0]), "+f"(d[1]), "+f"(d[2]), "+f"(d[3])
        : "r"(a[0]), "r"(a[1]), "r"(a[2]), "r"(a[3]), "r"(b0), "r"(b1));
}
__device__ __forceinline__ void cpa16(uint32_t dst, const void* src) {
    asm volatile("cp.async.cg.shared.global [%0], [%1], 16;" :: "r"(dst), "l"(src));
}
__device__ __forceinline__ uint32_t packbf(float a, float b) {
    __nv_bfloat16 ha = __float2bfloat16(a), hb = __float2bfloat16(b);
    return (uint32_t)__bfloat16_as_ushort(ha) |
           ((uint32_t)__bfloat16_as_ushort(hb) << 16);
}

// ===========================================================================
// Kernel 0: convert x and W to bf16 hi/lo pairs.
// ===========================================================================
__global__ __launch_bounds__(256) void cvt_kernel(
    const float* __restrict__ x,
    const float* __restrict__ Wq, const float* __restrict__ Wk,
    const float* __restrict__ Wv)
{
    const size_t NX = (size_t)ROWS * DM;          // 16,777,216
    size_t i4 = ((size_t)blockIdx.x * 256 + threadIdx.x) * 4;

    const float* src;
    __nv_bfloat16 *dh, *dl;
    size_t off;
    if (i4 < NX) {
        src = x; off = i4; dh = g_xh; dl = g_xl;
    } else {
        size_t j = i4 - NX;
        if (j >= (size_t)3 * D * DM) return;
        size_t w = j >> 17;                        // /131072
        src = (w == 0) ? Wq : (w == 1) ? Wk : Wv;
        off = j & 131071;
        dh = g_wh + (j - off) ; dl = g_wl + (j - off);
        dh += 0; dl += 0;   // base at w*131072 handled below
        dh = g_wh + (w << 17); dl = g_wl + (w << 17);
    }
    float4 v = *(const float4*)&src[off];
    __nv_bfloat16 h0 = __float2bfloat16(v.x), h1 = __float2bfloat16(v.y);
    __nv_bfloat16 h2 = __float2bfloat16(v.z), h3 = __float2bfloat16(v.w);
    float l0 = v.x - __bfloat162float(h0), l1 = v.y - __bfloat162float(h1);
    float l2 = v.z - __bfloat162float(h2), l3 = v.w - __bfloat162float(h3);
    uint2 hp, lp;
    hp.x = (uint32_t)__bfloat16_as_ushort(h0) | ((uint32_t)__bfloat16_as_ushort(h1) << 16);
    hp.y = (uint32_t)__bfloat16_as_ushort(h2) | ((uint32_t)__bfloat16_as_ushort(h3) << 16);
    lp.x = packbf(l0, l1);
    lp.y = packbf(l2, l3);
    *(uint2*)&dh[off] = hp;
    *(uint2*)&dl[off] = lp;
}

// ===========================================================================
// Kernel 1: QKV projection on tensor cores (mma.sync bf16, 3-term hi/lo).
// C[row, d] = sum_m x[row,m] * W[d,m] + b[d]; A row-major, B ([d][m]) col-major
// for the mma => "row.col" layout with no transposes anywhere.
// Tiles: CTA 128(M) x 128(N) x 32(K). 8 warps = 4(M) x 2(N), warp 32x64.
// smem: 4 bf16 tiles (Ah, Al, Bh, Bl) of 128 x 32, row stride 40 elems (80B),
// double buffered -> 81920 B dynamic.
// ===========================================================================
#define TSTRIDE 80                 // bytes per tile row
#define TILE_B  (128 * TSTRIDE)    // 10240
#define STAGE_B (4 * TILE_B)       // 40960

__global__ __launch_bounds__(256, 2) void qkv_mma_kernel(
    const float* __restrict__ bq, const float* __restrict__ bk,
    const float* __restrict__ bv)
{
    extern __shared__ char smem[];
    const uint32_t sb = s2u(smem);

    const int tid  = threadIdx.x;
    const int lane = tid & 31;
    const int wid  = tid >> 5;
    const int wm   = wid & 3;        // M block (32 rows)
    const int wn   = wid >> 2;       // N block (64 cols)
    const int head = blockIdx.y;
    const int row0 = blockIdx.x * 128;

    const __nv_bfloat16* Ahg = g_xh + (size_t)row0 * DM;
    const __nv_bfloat16* Alg = g_xl + (size_t)row0 * DM;
    const __nv_bfloat16* Bhg = g_wh + ((size_t)head << 17);
    const __nv_bfloat16* Blg = g_wl + ((size_t)head << 17);
    const float* bias = (head == 0) ? bq : (head == 1) ? bk : bv;
    float* out = (head == 0) ? g_q : (head == 1) ? g_k : g_v;

    // cp.async issue for chunk c: each thread copies 2x16B per tile.
    const int cr  = tid >> 1;             // row 0..127
    const int ccu = (tid & 1) * 2;        // 16B-unit 0 or 2
    const uint32_t cdoff = (uint32_t)(cr * TSTRIDE + ccu * 16);

    #define ISSUE(c) do {                                                    \
        int _buf = (c) & 1;                                                  \
        uint32_t _b = sb + _buf * STAGE_B;                                   \
        size_t _g = (size_t)cr * DM + (c) * 32 + ccu * 8;                    \
        cpa16(_b + 0*TILE_B + cdoff,      Ahg + _g);                         \
        cpa16(_b + 0*TILE_B + cdoff + 16, Ahg + _g + 8);                     \
        cpa16(_b + 1*TILE_B + cdoff,      Alg + _g);                         \
        cpa16(_b + 1*TILE_B + cdoff + 16, Alg + _g + 8);                     \
        cpa16(_b + 2*TILE_B + cdoff,      Bhg + _g);                         \
        cpa16(_b + 2*TILE_B + cdoff + 16, Bhg + _g + 8);                     \
        cpa16(_b + 3*TILE_B + cdoff,      Blg + _g);                         \
        cpa16(_b + 3*TILE_B + cdoff + 16, Blg + _g + 8);                     \
    } while (0)

    float acc[2][8][4];
    #pragma unroll
    for (int i = 0; i < 2; i++)
        #pragma unroll
        for (int j = 0; j < 8; j++)
            #pragma unroll
            for (int q = 0; q < 4; q++) acc[i][j][q] = 0.0f;

    ISSUE(0);
    asm volatile("cp.async.commit_group;" ::: "memory");
    ISSUE(1);
    asm volatile("cp.async.commit_group;" ::: "memory");

    // ldmatrix lane addressing (conflict-free with 80B row stride)
    const uint32_t lrA = (uint32_t)(wm * 32 + (lane & 15));
    const uint32_t lrB = (uint32_t)(wn * 64 + (lane & 15));
    const uint32_t lcb = (uint32_t)((lane >> 4) << 4);

    for (int c = 0; c < NCH; c++) {
        asm volatile("cp.async.wait_group 1;" ::: "memory");
        __syncthreads();

        uint32_t base = sb + (c & 1) * STAGE_B;
        uint32_t aH = base, aL = base + TILE_B;
        uint32_t bH = base + 2 * TILE_B, bL = base + 3 * TILE_B;

        #pragma unroll
        for (int ks = 0; ks < 2; ks++) {
            uint32_t kb = (uint32_t)(ks * 32) + lcb;
            uint32_t ah[8], al[8];
            ldsm4(ah,     aH + lrA * TSTRIDE + kb);
            ldsm4(ah + 4, aH + (lrA + 16) * TSTRIDE + kb);
            ldsm4(al,     aL + lrA * TSTRIDE + kb);
            ldsm4(al + 4, aL + (lrA + 16) * TSTRIDE + kb);
            #pragma unroll
            for (int nb = 0; nb < 4; nb++) {
                uint32_t bh[4], bl[4];
                ldsm4(bh, bH + (lrB + nb * 16) * TSTRIDE + kb);
                ldsm4(bl, bL + (lrB + nb * 16) * TSTRIDE + kb);
                #pragma unroll
                for (int ma = 0; ma < 2; ma++) {
                    // atoms: even n: {r0, r2}; odd n: {r1, r3}
                    mma_bf16(acc[ma][nb*2+0], ah + ma*4, bh[0], bh[2]);
                    mma_bf16(acc[ma][nb*2+1], ah + ma*4, bh[1], bh[3]);
                    mma_bf16(acc[ma][nb*2+0], al + ma*4, bh[0], bh[2]);
                    mma_bf16(acc[ma][nb*2+1], al + ma*4, bh[1], bh[3]);
                    mma_bf16(acc[ma][nb*2+0], ah + ma*4, bl[0], bl[2]);
                    mma_bf16(acc[ma][nb*2+1], ah + ma*4, bl[1], bl[3]);
                }
            }
        }
        __syncthreads();
        if (c + 2 < NCH) ISSUE(c + 2);
        asm volatile("cp.async.commit_group;" ::: "memory");
    }

    // Epilogue: bias add, fp32 store.
    const int groupID = lane >> 2;
    const int tid4    = lane & 3;
    #pragma unroll
    for (int ma = 0; ma < 2; ma++) {
        int r = row0 + wm * 32 + ma * 16 + groupID;
        #pragma unroll
        for (int na = 0; na < 8; na++) {
            int col = wn * 64 + na * 8 + tid4 * 2;
            float bx = __ldg(&bias[col]), by = __ldg(&bias[col + 1]);
            float2 v0 = { acc[ma][na][0] + bx, acc[ma][na][1] + by };
            float2 v1 = { acc[ma][na][2] + bx, acc[ma][na][3] + by };
            *(float2*)&out[(size_t)r * D + col] = v0;
            *(float2*)&out[(size_t)(r + 8) * D + col] = v1;
        }
    }
}

// ---------------------------------------------------------------------------
// Kernel 2a: split-K partials of M_b = K_b^T V_b  ([128,128] per batch).
// ---------------------------------------------------------------------------
__global__ __launch_bounds__(256) void ktv_partial_kernel()
{
    const int b     = blockIdx.y;
    const int split = blockIdx.x;
    const int t0    = split * (SEQ / SPLITS);

    const float* kb = g_k + (size_t)b * SEQ * D;
    const float* vb = g_v + (size_t)b * SEQ * D;

    __shared__ float Ks[16][D];
    __shared__ float Vs[16][D];

    const int tid = threadIdx.x;
    const int tx  = tid & 15;
    const int ty  = tid >> 4;

    float acc[8][8];
    #pragma unroll
    for (int i = 0; i < 8; i++)
        #pragma unroll
        for (int j = 0; j < 8; j++) acc[i][j] = 0.0f;

    for (int tt = 0; tt < SEQ / SPLITS; tt += 16) {
        #pragma unroll
        for (int i = 0; i < 2; i++) {
            int slot = tid + i * 256;
            int r  = slot >> 5;
            int c4 = (slot & 31) * 4;
            *(float4*)&Ks[r][c4] = *(const float4*)&kb[(size_t)(t0 + tt + r) * D + c4];
            *(float4*)&Vs[r][c4] = *(const float4*)&vb[(size_t)(t0 + tt + r) * D + c4];
        }
        __syncthreads();

        #pragma unroll
        for (int kk = 0; kk < 16; kk++) {
            float ra[8], rb[8];
            *(float4*)&ra[0] = *(float4*)&Ks[kk][ty * 8];
            *(float4*)&ra[4] = *(float4*)&Ks[kk][ty * 8 + 4];
            *(float4*)&rb[0] = *(float4*)&Vs[kk][tx * 8];
            *(float4*)&rb[4] = *(float4*)&Vs[kk][tx * 8 + 4];
            #pragma unroll
            for (int i = 0; i < 8; i++)
                #pragma unroll
                for (int j = 0; j < 8; j++)
                    acc[i][j] += ra[i] * rb[j];
        }
        __syncthreads();
    }

    float* outp = g_mpart + ((size_t)(b * SPLITS + split)) * D * D;
    #pragma unroll
    for (int i = 0; i < 8; i++) {
        int r = ty * 8 + i;
        #pragma unroll
        for (int jv = 0; jv < 2; jv++) {
            int c = tx * 8 + jv * 4;
            *(float4*)&outp[(size_t)r * D + c] = *(float4*)&acc[i][jv * 4];
        }
    }
}

// ---------------------------------------------------------------------------
// Kernel 2b: reduce the 32 split partials into g_m.
// ---------------------------------------------------------------------------
__global__ __launch_bounds__(256) void reduce_m_kernel()
{
    int idx = blockIdx.x * 256 + threadIdx.x;
    int b   = idx >> 14;
    int ij  = idx & 16383;
    float s = 0.0f;
    #pragma unroll
    for (int p = 0; p < SPLITS; p++)
        s += g_mpart[(((size_t)(b * SPLITS + p)) << 14) + ij];
    g_m[idx] = s;
}

// ---------------------------------------------------------------------------
// Kernel 3: out[b,s,:] = scale * q[b,s,:] @ M_b.  NN GEMM, K=128.
// ---------------------------------------------------------------------------
__global__ __launch_bounds__(256, 2) void out_kernel(float* __restrict__ out)
{
    const int b  = blockIdx.y;
    const int s0 = blockIdx.x * 128;

    const float* q = g_q + (size_t)b * SEQ * D;
    const float* M = g_m + (size_t)b * D * D;

    __shared__ float As[32][128 + PAD];
    __shared__ float Bs[32][128 + PAD];

    const int tid = threadIdx.x;
    const int tx  = tid & 15;
    const int ty  = tid >> 4;

    float acc[8][8];
    #pragma unroll
    for (int i = 0; i < 8; i++)
        #pragma unroll
        for (int j = 0; j < 8; j++) acc[i][j] = 0.0f;

    for (int kt = 0; kt < D; kt += 32) {
        #pragma unroll
        for (int i = 0; i < 4; i++) {
            int slot = tid + i * 256;
            int r  = slot >> 3;
            int c4 = (slot & 7) * 4;
            float4 va = *(const float4*)&q[(size_t)(s0 + r) * D + kt + c4];
            As[c4 + 0][r] = va.x; As[c4 + 1][r] = va.y;
            As[c4 + 2][r] = va.z; As[c4 + 3][r] = va.w;
        }
        #pragma unroll
        for (int i = 0; i < 4; i++) {
            int slot = tid + i * 256;
            int dr = slot >> 5;
            int c4 = (slot & 31) * 4;
            *(float4*)&Bs[dr][c4] = *(const float4*)&M[(size_t)(kt + dr) * D + c4];
        }
        __syncthreads();

        #pragma unroll
        for (int kk = 0; kk < 32; kk++) {
            float ra[8], rb[8];
            *(float4*)&ra[0] = *(float4*)&As[kk][ty * 8];
            *(float4*)&ra[4] = *(float4*)&As[kk][ty * 8 + 4];
            *(float4*)&rb[0] = *(float4*)&Bs[kk][tx * 8];
            *(float4*)&rb[4] = *(float4*)&Bs[kk][tx * 8 + 4];
            #pragma unroll
            for (int i = 0; i < 8; i++)
                #pragma unroll
                for (int j = 0; j < 8; j++)
                    acc[i][j] += ra[i] * rb[j];
        }
        __syncthreads();
    }

    const float scale = 0.08838834764831845f;
    #pragma unroll
    for (int i = 0; i < 8; i++) {
        int s = s0 + ty * 8 + i;
        #pragma unroll
        for (int jv = 0; jv < 2; jv++) {
            int c = tx * 8 + jv * 4;
            float4 o;
            o.x = acc[i][jv * 4 + 0] * scale;
            o.y = acc[i][jv * 4 + 1] * scale;
            o.z = acc[i][jv * 4 + 2] * scale;
            o.w = acc[i][jv * 4 + 3] * scale;
            *(float4*)&out[((size_t)b * SEQ + s) * D + c] = o;
        }
    }
}

// ---------------------------------------------------------------------------
extern "C" void kernel_launch(void* const* d_in, const int* in_sizes, int n_in,
                              void* d_out, int out_size)
{
    const float* x  = (const float*)d_in[0];
    const float* Wq = (const float*)d_in[1];
    const float* bq = (const float*)d_in[2];
    const float* Wk = (const float*)d_in[3];
    const float* bk = (const float*)d_in[4];
    const float* Wv = (const float*)d_in[5];
    const float* bv = (const float*)d_in[6];
    float* out = (float*)d_out;

    static bool attr_set = false;
    if (!attr_set) {
        cudaFuncSetAttribute(qkv_mma_kernel,
                             cudaFuncAttributeMaxDynamicSharedMemorySize,
                             2 * STAGE_B);
        attr_set = true;
    }

    // total elements to convert: x (16.7M) + 3 W (0.39M) -> 16768 blocks of 256x4
    cvt_kernel<<<dim3(16768), 256>>>(x, Wq, Wk, Wv);
    qkv_mma_kernel<<<dim3(ROWS / 128, 3), 256, 2 * STAGE_B>>>(bq, bk, bv);
    ktv_partial_kernel<<<dim3(SPLITS, BATCH), 256>>>();
    reduce_m_kernel<<<dim3(BATCH * D * D / 256), 256>>>();
    out_kernel<<<dim3(SEQ / 128, BATCH), 256>>>(out);
}

// round 4
// speedup vs baseline: 2.7302x; 1.5651x over previous
#include <cuda_runtime.h>
#include <cuda_fp16.h>
#include <cstdint>

#define D      128
#define DM     1024
#define BATCH  4
#define SEQ    4096
#define ROWS   (BATCH * SEQ)   // 16384
#define TSPL   32              // ktv split count
#define NCH2   16              // qkv K chunks of 64

// Scratch (allocation-free rule: __device__ globals)
__device__ __half g_xh[(size_t)ROWS * DM];
__device__ __half g_xl[(size_t)ROWS * DM];
__device__ __half g_wh[3 * D * DM];
__device__ __half g_qh[ROWS * D];
__device__ __half g_ql[ROWS * D];
__device__ __half g_kh[ROWS * D];
__device__ __half g_kl[ROWS * D];
__device__ __half g_vh[ROWS * D];
__device__ __half g_vl[ROWS * D];
__device__ float  g_mpart[BATCH * TSPL * D * D];
__device__ __half g_mh[BATCH * D * D];
__device__ __half g_ml[BATCH * D * D];

// ===========================================================================
// helpers (sm_80-era PTX: ldmatrix / mma.sync / cp.async)
// ===========================================================================
__device__ __forceinline__ uint32_t s2u(const void* p) {
    uint32_t a;
    asm("{ .reg .u64 t; cvta.to.shared.u64 t, %1; cvt.u32.u64 %0, t; }"
        : "=r"(a) : "l"(p));
    return a;
}
__device__ __forceinline__ void ldsm4(uint32_t* r, uint32_t addr) {
    asm volatile("ldmatrix.sync.aligned.m8n8.x4.shared.b16 {%0,%1,%2,%3}, [%4];"
                 : "=r"(r[0]), "=r"(r[1]), "=r"(r[2]), "=r"(r[3]) : "r"(addr));
}
__device__ __forceinline__ void ldsm4t(uint32_t* r, uint32_t addr) {
    asm volatile("ldmatrix.sync.aligned.m8n8.x4.trans.shared.b16 {%0,%1,%2,%3}, [%4];"
                 : "=r"(r[0]), "=r"(r[1]), "=r"(r[2]), "=r"(r[3]) : "r"(addr));
}
__device__ __forceinline__ void mma_fp16(float* d, const uint32_t* a,
                                         uint32_t b0, uint32_t b1) {
    asm volatile(
        "mma.sync.aligned.m16n8k16.row.col.f32.f16.f16.f32 "
        "{%0,%1,%2,%3}, {%4,%5,%6,%7}, {%8,%9}, {%0,%1,%2,%3};"
        : "+f"(d[0]), "+f"(d[1]), "+f"(d[2]), "+f"(d[3])
        : "r"(a[0]), "r"(a[1]), "r"(a[2]), "r"(a[3]), "r"(b0), "r"(b1));
}
__device__ __forceinline__ void cpa16(uint32_t dst, const void* src) {
    asm volatile("cp.async.cg.shared.global [%0], [%1], 16;" :: "r"(dst), "l"(src));
}

// ===========================================================================
// Kernel 0: convert x -> fp16 hi/lo; W -> fp16 hi only.
// ===========================================================================
__global__ __launch_bounds__(256) void cvt_kernel(
    const float* __restrict__ x,
    const float* __restrict__ Wq, const float* __restrict__ Wk,
    const float* __restrict__ Wv)
{
    const size_t NX = (size_t)ROWS * DM;           // 16,777,216
    size_t i4 = ((size_t)blockIdx.x * 256 + threadIdx.x) * 4;

    if (i4 < NX) {
        float4 v = *(const float4*)&x[i4];
        __half h0 = __float2half_rn(v.x), h1 = __float2half_rn(v.y);
        __half h2 = __float2half_rn(v.z), h3 = __float2half_rn(v.w);
        __half l0 = __float2half_rn(v.x - __half2float(h0));
        __half l1 = __float2half_rn(v.y - __half2float(h1));
        __half l2 = __float2half_rn(v.z - __half2float(h2));
        __half l3 = __float2half_rn(v.w - __half2float(h3));
        __half2 hp0 = __halves2half2(h0, h1), hp1 = __halves2half2(h2, h3);
        __half2 lp0 = __halves2half2(l0, l1), lp1 = __halves2half2(l2, l3);
        *(__half2*)&g_xh[i4]     = hp0;
        *(__half2*)&g_xh[i4 + 2] = hp1;
        *(__half2*)&g_xl[i4]     = lp0;
        *(__half2*)&g_xl[i4 + 2] = lp1;
    } else {
        size_t j = i4 - NX;
        if (j >= (size_t)3 * D * DM) return;
        size_t w = j >> 17;                         // which W
        const float* src = (w == 0) ? Wq : (w == 1) ? Wk : Wv;
        size_t off = j & 131071;
        float4 v = *(const float4*)&src[off];
        __half2 hp0 = __halves2half2(__float2half_rn(v.x), __float2half_rn(v.y));
        __half2 hp1 = __halves2half2(__float2half_rn(v.z), __float2half_rn(v.w));
        *(__half2*)&g_wh[j]     = hp0;
        *(__half2*)&g_wh[j + 2] = hp1;
    }
}

// ===========================================================================
// Kernel 1: QKV projection, 2-term fp16 mma.
// C[row,d] = x[row,:] . W[d,:] + b[d]; A = xh+xl (hi/lo), B = Wh only.
// CTA 128x128xK64 double buffered; warps 4M x 2N (warp 32x64).
// Outputs fp16 hi/lo pairs per head.
// ===========================================================================
#define TS2   144                 // smem bytes per row (128 data + 16 pad)
#define TILE2 (128 * TS2)         // 18432
#define STG2  (3 * TILE2)         // 55296 per stage (Ah, Al, Bh)

__global__ __launch_bounds__(256, 2) void qkv_mma_kernel(
    const float* __restrict__ bq, const float* __restrict__ bk,
    const float* __restrict__ bv)
{
    extern __shared__ char smem[];
    const uint32_t sb = s2u(smem);

    const int tid  = threadIdx.x;
    const int lane = tid & 31;
    const int wid  = tid >> 5;
    const int wm   = wid & 3;        // 32-row M block
    const int wn   = wid >> 2;       // 64-col N block
    const int head = blockIdx.y;
    const int row0 = blockIdx.x * 128;

    const __half* Ahg = g_xh + (size_t)row0 * DM;
    const __half* Alg = g_xl + (size_t)row0 * DM;
    const __half* Bhg = g_wh + ((size_t)head << 17);
    const float* bias = (head == 0) ? bq : (head == 1) ? bk : bv;
    __half* oh = (head == 0) ? g_qh : (head == 1) ? g_kh : g_vh;
    __half* ol = (head == 0) ? g_ql : (head == 1) ? g_kl : g_vl;

    // cp.async mapping: 128 rows x 8 16B-units = 1024 slots, 4 per thread/tile.
    int cr[4], cu[4];
    #pragma unroll
    for (int i = 0; i < 4; i++) {
        int slot = tid + i * 256;
        cr[i] = slot >> 3;
        cu[i] = slot & 7;
    }

    #define QISSUE(c) do {                                                     \
        uint32_t _b = sb + ((c) & 1) * STG2;                                   \
        _Pragma("unroll")                                                      \
        for (int _i = 0; _i < 4; _i++) {                                       \
            uint32_t _so = (uint32_t)(cr[_i] * TS2 + cu[_i] * 16);             \
            size_t _go = (size_t)cr[_i] * DM + (c) * 64 + cu[_i] * 8;          \
            cpa16(_b + _so,             Ahg + _go);                            \
            cpa16(_b + TILE2 + _so,     Alg + _go);                            \
            cpa16(_b + 2 * TILE2 + _so, Bhg + _go);                            \
        }                                                                      \
    } while (0)

    float acc[2][8][4];
    #pragma unroll
    for (int i = 0; i < 2; i++)
        #pragma unroll
        for (int j = 0; j < 8; j++)
            #pragma unroll
            for (int q = 0; q < 4; q++) acc[i][j][q] = 0.0f;

    QISSUE(0);
    asm volatile("cp.async.commit_group;" ::: "memory");
    QISSUE(1);
    asm volatile("cp.async.commit_group;" ::: "memory");

    const uint32_t lrA = (uint32_t)(wm * 32 + (lane & 15));
    const uint32_t lcb = (uint32_t)((lane >> 4) << 4);

    for (int c = 0; c < NCH2; c++) {
        asm volatile("cp.async.wait_group 1;" ::: "memory");
        __syncthreads();

        uint32_t base = sb + (c & 1) * STG2;
        uint32_t aH = base, aL = base + TILE2, bH = base + 2 * TILE2;

        #pragma unroll
        for (int ks = 0; ks < 4; ks++) {
            uint32_t kb = (uint32_t)(ks * 32) + lcb;
            uint32_t ah[8], al[8];
            ldsm4(ah,     aH + lrA * TS2 + kb);
            ldsm4(ah + 4, aH + (lrA + 16) * TS2 + kb);
            ldsm4(al,     aL + lrA * TS2 + kb);
            ldsm4(al + 4, aL + (lrA + 16) * TS2 + kb);
            #pragma unroll
            for (int nb = 0; nb < 4; nb++) {
                uint32_t rb = (uint32_t)(wn * 64 + nb * 16 + (lane & 15));
                uint32_t bh[4];
                ldsm4(bh, bH + rb * TS2 + kb);
                #pragma unroll
                for (int ma = 0; ma < 2; ma++) {
                    mma_fp16(acc[ma][nb*2+0], ah + ma*4, bh[0], bh[2]);
                    mma_fp16(acc[ma][nb*2+1], ah + ma*4, bh[1], bh[3]);
                    mma_fp16(acc[ma][nb*2+0], al + ma*4, bh[0], bh[2]);
                    mma_fp16(acc[ma][nb*2+1], al + ma*4, bh[1], bh[3]);
                }
            }
        }
        __syncthreads();
        if (c + 2 < NCH2) QISSUE(c + 2);
        asm volatile("cp.async.commit_group;" ::: "memory");
    }

    // Epilogue: add bias, split fp32 -> fp16 hi/lo, store.
    const int g8  = lane >> 2;
    const int t4  = lane & 3;
    #pragma unroll
    for (int ma = 0; ma < 2; ma++) {
        int r = row0 + wm * 32 + ma * 16 + g8;
        #pragma unroll
        for (int na = 0; na < 8; na++) {
            int col = wn * 64 + na * 8 + t4 * 2;
            float bx = __ldg(&bias[col]), by = __ldg(&bias[col + 1]);
            float v0x = acc[ma][na][0] + bx, v0y = acc[ma][na][1] + by;
            float v1x = acc[ma][na][2] + bx, v1y = acc[ma][na][3] + by;
            __half h0x = __float2half_rn(v0x), h0y = __float2half_rn(v0y);
            __half h1x = __float2half_rn(v1x), h1y = __float2half_rn(v1y);
            __half l0x = __float2half_rn(v0x - __half2float(h0x));
            __half l0y = __float2half_rn(v0y - __half2float(h0y));
            __half l1x = __float2half_rn(v1x - __half2float(h1x));
            __half l1y = __float2half_rn(v1y - __half2float(h1y));
            *(__half2*)&oh[(size_t)r * D + col]       = __halves2half2(h0x, h0y);
            *(__half2*)&ol[(size_t)r * D + col]       = __halves2half2(l0x, l0y);
            *(__half2*)&oh[(size_t)(r + 8) * D + col] = __halves2half2(h1x, h1y);
            *(__half2*)&ol[(size_t)(r + 8) * D + col] = __halves2half2(l1x, l1y);
        }
    }
}

// ===========================================================================
// Kernel 2a: ktv partials on tensor cores, 3-term fp16.
// M_part[d,e] = sum_{t in split} k[t,d] * v[t,e].
// A = k^T via ldmatrix.trans; B = v via ldmatrix.trans. K = 128 t-rows.
// ===========================================================================
#define TS3   272                 // 256 data + 16 pad
#define TILE3 (128 * TS3)         // 34816

__global__ __launch_bounds__(256) void ktv_mma_kernel()
{
    extern __shared__ char smem[];
    const uint32_t sb = s2u(smem);
    const uint32_t sKh = sb, sKl = sb + TILE3, sVh = sb + 2*TILE3, sVl = sb + 3*TILE3;

    const int tid  = threadIdx.x;
    const int lane = tid & 31;
    const int wid  = tid >> 5;
    const int wm   = wid & 3;        // d block (32)
    const int wn   = wid >> 2;       // e block (64)
    const int b    = blockIdx.y;
    const int t0   = blockIdx.x * 128;

    const __half* khg = g_kh + ((size_t)b * SEQ + t0) * D;
    const __half* klg = g_kl + ((size_t)b * SEQ + t0) * D;
    const __half* vhg = g_vh + ((size_t)b * SEQ + t0) * D;
    const __half* vlg = g_vl + ((size_t)b * SEQ + t0) * D;

    // Load all four 128x128 fp16 tiles (128KB) via cp.async.
    #pragma unroll
    for (int i = 0; i < 8; i++) {
        int slot = tid + i * 256;          // 2048 slots: 128 rows x 16 units
        int r = slot >> 4, u = slot & 15;
        uint32_t so = (uint32_t)(r * TS3 + u * 16);
        size_t go = (size_t)r * D + u * 8;
        cpa16(sKh + so, khg + go);
        cpa16(sKl + so, klg + go);
        cpa16(sVh + so, vhg + go);
        cpa16(sVl + so, vlg + go);
    }
    asm volatile("cp.async.commit_group;" ::: "memory");
    asm volatile("cp.async.wait_group 0;" ::: "memory");
    __syncthreads();

    float acc[2][8][4];
    #pragma unroll
    for (int i = 0; i < 2; i++)
        #pragma unroll
        for (int j = 0; j < 8; j++)
            #pragma unroll
            for (int q = 0; q < 4; q++) acc[i][j][q] = 0.0f;

    const uint32_t trow = (uint32_t)(((lane >> 4) & 1) * 8 + (lane & 7));
    const uint32_t tcb  = (uint32_t)(((lane >> 3) & 1) * 16);

    #pragma unroll
    for (int ks = 0; ks < 8; ks++) {
        uint32_t abase = (uint32_t)(ks * 16) + trow;     // t row within tile
        uint32_t aoff = abase * TS3 + tcb;
        uint32_t ah[8], al[8];
        ldsm4t(ah,     sKh + aoff + wm * 64);
        ldsm4t(ah + 4, sKh + aoff + wm * 64 + 32);
        ldsm4t(al,     sKl + aoff + wm * 64);
        ldsm4t(al + 4, sKl + aoff + wm * 64 + 32);
        #pragma unroll
        for (int nb = 0; nb < 4; nb++) {
            uint32_t eb = (uint32_t)(wn * 128 + nb * 32);
            uint32_t bh[4], bl[4];
            ldsm4t(bh, sVh + aoff + eb);
            ldsm4t(bl, sVl + aoff + eb);
            #pragma unroll
            for (int ma = 0; ma < 2; ma++) {
                mma_fp16(acc[ma][nb*2+0], ah + ma*4, bh[0], bh[2]);
                mma_fp16(acc[ma][nb*2+1], ah + ma*4, bh[1], bh[3]);
                mma_fp16(acc[ma][nb*2+0], al + ma*4, bh[0], bh[2]);
                mma_fp16(acc[ma][nb*2+1], al + ma*4, bh[1], bh[3]);
                mma_fp16(acc[ma][nb*2+0], ah + ma*4, bl[0], bl[2]);
                mma_fp16(acc[ma][nb*2+1], ah + ma*4, bl[1], bl[3]);
            }
        }
    }

    float* outp = g_mpart + ((size_t)(b * TSPL + blockIdx.x) << 14);
    const int g8 = lane >> 2;
    const int t4 = lane & 3;
    #pragma unroll
    for (int ma = 0; ma < 2; ma++) {
        int r = wm * 32 + ma * 16 + g8;
        #pragma unroll
        for (int na = 0; na < 8; na++) {
            int col = wn * 64 + na * 8 + t4 * 2;
            *(float2*)&outp[(size_t)r * D + col] =
                make_float2(acc[ma][na][0], acc[ma][na][1]);
            *(float2*)&outp[(size_t)(r + 8) * D + col] =
                make_float2(acc[ma][na][2], acc[ma][na][3]);
        }
    }
}

// ===========================================================================
// Kernel 2b: reduce partials -> M, emit fp16 hi/lo.
// ===========================================================================
__global__ __launch_bounds__(256) void reduce_m_kernel()
{
    int idx = blockIdx.x * 256 + threadIdx.x;    // 0..65535
    int b   = idx >> 14;
    int ij  = idx & 16383;
    float s = 0.0f;
    #pragma unroll
    for (int p = 0; p < TSPL; p++)
        s += g_mpart[(((size_t)(b * TSPL + p)) << 14) + ij];
    __half h = __float2half_rn(s);
    g_mh[idx] = h;
    g_ml[idx] = __float2half_rn(s - __half2float(h));
}

// ===========================================================================
// Kernel 3: out = scale * q @ M on tensor cores, 3-term fp16.
// A = qh/ql [s][d] (non-trans); B = Mh/Ml [d][e] via ldmatrix.trans.
// ===========================================================================
__global__ __launch_bounds__(256) void out_mma_kernel(float* __restrict__ out)
{
    extern __shared__ char smem[];
    const uint32_t sb = s2u(smem);
    const uint32_t sQh = sb, sQl = sb + TILE3, sMh = sb + 2*TILE3, sMl = sb + 3*TILE3;

    const int tid  = threadIdx.x;
    const int lane = tid & 31;
    const int wid  = tid >> 5;
    const int wm   = wid & 3;        // s block (32)
    const int wn   = wid >> 2;       // e block (64)
    const int b    = blockIdx.y;
    const int s0   = blockIdx.x * 128;

    const __half* qhg = g_qh + ((size_t)b * SEQ + s0) * D;
    const __half* qlg = g_ql + ((size_t)b * SEQ + s0) * D;
    const __half* mhg = g_mh + ((size_t)b << 14);
    const __half* mlg = g_ml + ((size_t)b << 14);

    #pragma unroll
    for (int i = 0; i < 8; i++) {
        int slot = tid + i * 256;
        int r = slot >> 4, u = slot & 15;
        uint32_t so = (uint32_t)(r * TS3 + u * 16);
        size_t go = (size_t)r * D + u * 8;
        cpa16(sQh + so, qhg + go);
        cpa16(sQl + so, qlg + go);
        cpa16(sMh + so, mhg + go);
        cpa16(sMl + so, mlg + go);
    }
    asm volatile("cp.async.commit_group;" ::: "memory");
    asm volatile("cp.async.wait_group 0;" ::: "memory");
    __syncthreads();

    float acc[2][8][4];
    #pragma unroll
    for (int i = 0; i < 2; i++)
        #pragma unroll
        for (int j = 0; j < 8; j++)
            #pragma unroll
            for (int q = 0; q < 4; q++) acc[i][j][q] = 0.0f;

    const uint32_t lrA  = (uint32_t)(wm * 32 + (lane & 15));
    const uint32_t lcb  = (uint32_t)((lane >> 4) << 4);
    const uint32_t trow = (uint32_t)(((lane >> 4) & 1) * 8 + (lane & 7));
    const uint32_t tcb  = (uint32_t)(((lane >> 3) & 1) * 16);

    #pragma unroll
    for (int ks = 0; ks < 8; ks++) {
        uint32_t kb = (uint32_t)(ks * 32) + lcb;
        uint32_t ah[8], al[8];
        ldsm4(ah,     sQh + lrA * TS3 + kb);
        ldsm4(ah + 4, sQh + (lrA + 16) * TS3 + kb);
        ldsm4(al,     sQl + lrA * TS3 + kb);
        ldsm4(al + 4, sQl + (lrA + 16) * TS3 + kb);
        uint32_t boff = ((uint32_t)(ks * 16) + trow) * TS3 + tcb;
        #pragma unroll
        for (int nb = 0; nb < 4; nb++) {
            uint32_t eb = (uint32_t)(wn * 128 + nb * 32);
            uint32_t bh[4], bl[4];
            ldsm4t(bh, sMh + boff + eb);
            ldsm4t(bl, sMl + boff + eb);
            #pragma unroll
            for (int ma = 0; ma < 2; ma++) {
                mma_fp16(acc[ma][nb*2+0], ah + ma*4, bh[0], bh[2]);
                mma_fp16(acc[ma][nb*2+1], ah + ma*4, bh[1], bh[3]);
                mma_fp16(acc[ma][nb*2+0], al + ma*4, bh[0], bh[2]);
                mma_fp16(acc[ma][nb*2+1], al + ma*4, bh[1], bh[3]);
                mma_fp16(acc[ma][nb*2+0], ah + ma*4, bl[0], bl[2]);
                mma_fp16(acc[ma][nb*2+1], ah + ma*4, bl[1], bl[3]);
            }
        }
    }

    const float scale = 0.08838834764831845f;    // 128^-0.5
    const int g8 = lane >> 2;
    const int t4 = lane & 3;
    #pragma unroll
    for (int ma = 0; ma < 2; ma++) {
        int r = s0 + wm * 32 + ma * 16 + g8;
        #pragma unroll
        for (int na = 0; na < 8; na++) {
            int col = wn * 64 + na * 8 + t4 * 2;
            *(float2*)&out[((size_t)b * SEQ + r) * D + col] =
                make_float2(acc[ma][na][0] * scale, acc[ma][na][1] * scale);
            *(float2*)&out[((size_t)b * SEQ + r + 8) * D + col] =
                make_float2(acc[ma][na][2] * scale, acc[ma][na][3] * scale);
        }
    }
}

// ---------------------------------------------------------------------------
extern "C" void kernel_launch(void* const* d_in, const int* in_sizes, int n_in,
                              void* d_out, int out_size)
{
    const float* x  = (const float*)d_in[0];
    const float* Wq = (const float*)d_in[1];
    const float* bq = (const float*)d_in[2];
    const float* Wk = (const float*)d_in[3];
    const float* bk = (const float*)d_in[4];
    const float* Wv = (const float*)d_in[5];
    const float* bv = (const float*)d_in[6];
    float* out = (float*)d_out;

    cudaFuncSetAttribute(qkv_mma_kernel,
                         cudaFuncAttributeMaxDynamicSharedMemorySize, 2 * STG2);
    cudaFuncSetAttribute(ktv_mma_kernel,
                         cudaFuncAttributeMaxDynamicSharedMemorySize, 4 * TILE3);
    cudaFuncSetAttribute(out_mma_kernel,
                         cudaFuncAttributeMaxDynamicSharedMemorySize, 4 * TILE3);

    cvt_kernel<<<16768, 256>>>(x, Wq, Wk, Wv);
    qkv_mma_kernel<<<dim3(ROWS / 128, 3), 256, 2 * STG2>>>(bq, bk, bv);
    ktv_mma_kernel<<<dim3(TSPL, BATCH), 256, 4 * TILE3>>>();
    reduce_m_kernel<<<256, 256>>>();
    out_mma_kernel<<<dim3(SEQ / 128, BATCH), 256, 4 * TILE3>>>(out);
}

// round 5
// speedup vs baseline: 3.9324x; 1.4403x over previous
#include <cuda_runtime.h>
#include <cuda_fp16.h>
#include <cstdint>

#define D      128
#define DM     1024
#define BATCH  4
#define SEQ    4096
#define ROWS   (BATCH * SEQ)   // 16384
#define TSPL   32              // ktv split count
#define NCH2   16              // qkv K chunks of 64

// Scratch (allocation-free rule: __device__ globals)
__device__ __half g_xh[(size_t)ROWS * DM];
__device__ __half g_wh[3 * D * DM];
__device__ __half g_qh[ROWS * D];
__device__ __half g_ql[ROWS * D];
__device__ __half g_kh[ROWS * D];
__device__ __half g_kl[ROWS * D];
__device__ __half g_vh[ROWS * D];
__device__ __half g_vl[ROWS * D];
__device__ float  g_mpart[BATCH * TSPL * D * D];
__device__ __half g_mh[BATCH * D * D];
__device__ __half g_ml[BATCH * D * D];

// ===========================================================================
// helpers (sm_80-era PTX: ldmatrix / mma.sync / cp.async)
// ===========================================================================
__device__ __forceinline__ uint32_t s2u(const void* p) {
    uint32_t a;
    asm("{ .reg .u64 t; cvta.to.shared.u64 t, %1; cvt.u32.u64 %0, t; }"
        : "=r"(a) : "l"(p));
    return a;
}
__device__ __forceinline__ void ldsm4(uint32_t* r, uint32_t addr) {
    asm volatile("ldmatrix.sync.aligned.m8n8.x4.shared.b16 {%0,%1,%2,%3}, [%4];"
                 : "=r"(r[0]), "=r"(r[1]), "=r"(r[2]), "=r"(r[3]) : "r"(addr));
}
__device__ __forceinline__ void ldsm4t(uint32_t* r, uint32_t addr) {
    asm volatile("ldmatrix.sync.aligned.m8n8.x4.trans.shared.b16 {%0,%1,%2,%3}, [%4];"
                 : "=r"(r[0]), "=r"(r[1]), "=r"(r[2]), "=r"(r[3]) : "r"(addr));
}
__device__ __forceinline__ void mma_fp16(float* d, const uint32_t* a,
                                         uint32_t b0, uint32_t b1) {
    asm volatile(
        "mma.sync.aligned.m16n8k16.row.col.f32.f16.f16.f32 "
        "{%0,%1,%2,%3}, {%4,%5,%6,%7}, {%8,%9}, {%0,%1,%2,%3};"
        : "+f"(d[0]), "+f"(d[1]), "+f"(d[2]), "+f"(d[3])
        : "r"(a[0]), "r"(a[1]), "r"(a[2]), "r"(a[3]), "r"(b0), "r"(b1));
}
__device__ __forceinline__ void cpa16(uint32_t dst, const void* src) {
    asm volatile("cp.async.cg.shared.global [%0], [%1], 16;" :: "r"(dst), "l"(src));
}

// ===========================================================================
// Kernel 0: convert x -> fp16 hi; W -> fp16 hi.
// ===========================================================================
__global__ __launch_bounds__(256) void cvt_kernel(
    const float* __restrict__ x,
    const float* __restrict__ Wq, const float* __restrict__ Wk,
    const float* __restrict__ Wv)
{
    const size_t NX = (size_t)ROWS * DM;           // 16,777,216
    size_t i4 = ((size_t)blockIdx.x * 256 + threadIdx.x) * 4;

    if (i4 < NX) {
        float4 v = *(const float4*)&x[i4];
        __half2 hp0 = __halves2half2(__float2half_rn(v.x), __float2half_rn(v.y));
        __half2 hp1 = __halves2half2(__float2half_rn(v.z), __float2half_rn(v.w));
        *(__half2*)&g_xh[i4]     = hp0;
        *(__half2*)&g_xh[i4 + 2] = hp1;
    } else {
        size_t j = i4 - NX;
        if (j >= (size_t)3 * D * DM) return;
        size_t w = j >> 17;                         // which W
        const float* src = (w == 0) ? Wq : (w == 1) ? Wk : Wv;
        size_t off = j & 131071;
        float4 v = *(const float4*)&src[off];
        __half2 hp0 = __halves2half2(__float2half_rn(v.x), __float2half_rn(v.y));
        __half2 hp1 = __halves2half2(__float2half_rn(v.z), __float2half_rn(v.w));
        *(__half2*)&g_wh[j]     = hp0;
        *(__half2*)&g_wh[j + 2] = hp1;
    }
}

// ===========================================================================
// Kernel 1: QKV projection, 1-term fp16 mma.
// C[row,d] = x[row,:] . W[d,:] + b[d]; A = xh, B = Wh.
// CTA 128x128xK64 double buffered; warps 4M x 2N (warp 32x64).
// Outputs fp16 hi/lo pairs per head (downstream stays error-free class).
// ===========================================================================
#define TS2   144                 // smem bytes per row (128 data + 16 pad)
#define TILE2 (128 * TS2)         // 18432
#define STG2  (2 * TILE2)         // 36864 per stage (Ah, Bh)

__global__ __launch_bounds__(256, 2) void qkv_mma_kernel(
    const float* __restrict__ bq, const float* __restrict__ bk,
    const float* __restrict__ bv)
{
    extern __shared__ char smem[];
    const uint32_t sb = s2u(smem);

    const int tid  = threadIdx.x;
    const int lane = tid & 31;
    const int wid  = tid >> 5;
    const int wm   = wid & 3;        // 32-row M block
    const int wn   = wid >> 2;       // 64-col N block
    const int head = blockIdx.y;
    const int row0 = blockIdx.x * 128;

    const __half* Ahg = g_xh + (size_t)row0 * DM;
    const __half* Bhg = g_wh + ((size_t)head << 17);
    const float* bias = (head == 0) ? bq : (head == 1) ? bk : bv;
    __half* oh = (head == 0) ? g_qh : (head == 1) ? g_kh : g_vh;
    __half* ol = (head == 0) ? g_ql : (head == 1) ? g_kl : g_vl;

    // cp.async mapping: 128 rows x 8 16B-units = 1024 slots, 4 per thread/tile.
    int cr[4], cu[4];
    #pragma unroll
    for (int i = 0; i < 4; i++) {
        int slot = tid + i * 256;
        cr[i] = slot >> 3;
        cu[i] = slot & 7;
    }

    #define QISSUE(c) do {                                                     \
        uint32_t _b = sb + ((c) & 1) * STG2;                                   \
        _Pragma("unroll")                                                      \
        for (int _i = 0; _i < 4; _i++) {                                       \
            uint32_t _so = (uint32_t)(cr[_i] * TS2 + cu[_i] * 16);             \
            size_t _go = (size_t)cr[_i] * DM + (c) * 64 + cu[_i] * 8;          \
            cpa16(_b + _so,         Ahg + _go);                                \
            cpa16(_b + TILE2 + _so, Bhg + _go);                                \
        }                                                                      \
    } while (0)

    float acc[2][8][4];
    #pragma unroll
    for (int i = 0; i < 2; i++)
        #pragma unroll
        for (int j = 0; j < 8; j++)
            #pragma unroll
            for (int q = 0; q < 4; q++) acc[i][j][q] = 0.0f;

    QISSUE(0);
    asm volatile("cp.async.commit_group;" ::: "memory");
    QISSUE(1);
    asm volatile("cp.async.commit_group;" ::: "memory");

    const uint32_t lrA = (uint32_t)(wm * 32 + (lane & 15));
    const uint32_t lcb = (uint32_t)((lane >> 4) << 4);

    for (int c = 0; c < NCH2; c++) {
        asm volatile("cp.async.wait_group 1;" ::: "memory");
        __syncthreads();

        uint32_t base = sb + (c & 1) * STG2;
        uint32_t aH = base, bH = base + TILE2;

        #pragma unroll
        for (int ks = 0; ks < 4; ks++) {
            uint32_t kb = (uint32_t)(ks * 32) + lcb;
            uint32_t ah[8];
            ldsm4(ah,     aH + lrA * TS2 + kb);
            ldsm4(ah + 4, aH + (lrA + 16) * TS2 + kb);
            #pragma unroll
            for (int nb = 0; nb < 4; nb++) {
                uint32_t rb = (uint32_t)(wn * 64 + nb * 16 + (lane & 15));
                uint32_t bh[4];
                ldsm4(bh, bH + rb * TS2 + kb);
                #pragma unroll
                for (int ma = 0; ma < 2; ma++) {
                    mma_fp16(acc[ma][nb*2+0], ah + ma*4, bh[0], bh[2]);
                    mma_fp16(acc[ma][nb*2+1], ah + ma*4, bh[1], bh[3]);
                }
            }
        }
        __syncthreads();
        if (c + 2 < NCH2) QISSUE(c + 2);
        asm volatile("cp.async.commit_group;" ::: "memory");
    }

    // Epilogue: add bias, split fp32 -> fp16 hi/lo, store.
    const int g8  = lane >> 2;
    const int t4  = lane & 3;
    #pragma unroll
    for (int ma = 0; ma < 2; ma++) {
        int r = row0 + wm * 32 + ma * 16 + g8;
        #pragma unroll
        for (int na = 0; na < 8; na++) {
            int col = wn * 64 + na * 8 + t4 * 2;
            float bx = __ldg(&bias[col]), by = __ldg(&bias[col + 1]);
            float v0x = acc[ma][na][0] + bx, v0y = acc[ma][na][1] + by;
            float v1x = acc[ma][na][2] + bx, v1y = acc[ma][na][3] + by;
            __half h0x = __float2half_rn(v0x), h0y = __float2half_rn(v0y);
            __half h1x = __float2half_rn(v1x), h1y = __float2half_rn(v1y);
            __half l0x = __float2half_rn(v0x - __half2float(h0x));
            __half l0y = __float2half_rn(v0y - __half2float(h0y));
            __half l1x = __float2half_rn(v1x - __half2float(h1x));
            __half l1y = __float2half_rn(v1y - __half2float(h1y));
            *(__half2*)&oh[(size_t)r * D + col]       = __halves2half2(h0x, h0y);
            *(__half2*)&ol[(size_t)r * D + col]       = __halves2half2(l0x, l0y);
            *(__half2*)&oh[(size_t)(r + 8) * D + col] = __halves2half2(h1x, h1y);
            *(__half2*)&ol[(size_t)(r + 8) * D + col] = __halves2half2(l1x, l1y);
        }
    }
}

// ===========================================================================
// Kernel 2a: ktv partials on tensor cores, 3-term fp16.
// M_part[d,e] = sum_{t in split} k[t,d] * v[t,e].
// A = k^T via ldmatrix.trans; B = v via ldmatrix.trans. K = 128 t-rows.
// ===========================================================================
#define TS3   272                 // 256 data + 16 pad
#define TILE3 (128 * TS3)         // 34816

__global__ __launch_bounds__(256) void ktv_mma_kernel()
{
    extern __shared__ char smem[];
    const uint32_t sb = s2u(smem);
    const uint32_t sKh = sb, sKl = sb + TILE3, sVh = sb + 2*TILE3, sVl = sb + 3*TILE3;

    const int tid  = threadIdx.x;
    const int lane = tid & 31;
    const int wid  = tid >> 5;
    const int wm   = wid & 3;        // d block (32)
    const int wn   = wid >> 2;       // e block (64)
    const int b    = blockIdx.y;
    const int t0   = blockIdx.x * 128;

    const __half* khg = g_kh + ((size_t)b * SEQ + t0) * D;
    const __half* klg = g_kl + ((size_t)b * SEQ + t0) * D;
    const __half* vhg = g_vh + ((size_t)b * SEQ + t0) * D;
    const __half* vlg = g_vl + ((size_t)b * SEQ + t0) * D;

    // Load all four 128x128 fp16 tiles via cp.async.
    #pragma unroll
    for (int i = 0; i < 8; i++) {
        int slot = tid + i * 256;          // 2048 slots: 128 rows x 16 units
        int r = slot >> 4, u = slot & 15;
        uint32_t so = (uint32_t)(r * TS3 + u * 16);
        size_t go = (size_t)r * D + u * 8;
        cpa16(sKh + so, khg + go);
        cpa16(sKl + so, klg + go);
        cpa16(sVh + so, vhg + go);
        cpa16(sVl + so, vlg + go);
    }
    asm volatile("cp.async.commit_group;" ::: "memory");
    asm volatile("cp.async.wait_group 0;" ::: "memory");
    __syncthreads();

    float acc[2][8][4];
    #pragma unroll
    for (int i = 0; i < 2; i++)
        #pragma unroll
        for (int j = 0; j < 8; j++)
            #pragma unroll
            for (int q = 0; q < 4; q++) acc[i][j][q] = 0.0f;

    const uint32_t trow = (uint32_t)(((lane >> 4) & 1) * 8 + (lane & 7));
    const uint32_t tcb  = (uint32_t)(((lane >> 3) & 1) * 16);

    #pragma unroll
    for (int ks = 0; ks < 8; ks++) {
        uint32_t abase = (uint32_t)(ks * 16) + trow;     // t row within tile
        uint32_t aoff = abase * TS3 + tcb;
        uint32_t ah[8], al[8];
        ldsm4t(ah,     sKh + aoff + wm * 64);
        ldsm4t(ah + 4, sKh + aoff + wm * 64 + 32);
        ldsm4t(al,     sKl + aoff + wm * 64);
        ldsm4t(al + 4, sKl + aoff + wm * 64 + 32);
        #pragma unroll
        for (int nb = 0; nb < 4; nb++) {
            uint32_t eb = (uint32_t)(wn * 128 + nb * 32);
            uint32_t bh[4], bl[4];
            ldsm4t(bh, sVh + aoff + eb);
            ldsm4t(bl, sVl + aoff + eb);
            #pragma unroll
            for (int ma = 0; ma < 2; ma++) {
                mma_fp16(acc[ma][nb*2+0], ah + ma*4, bh[0], bh[2]);
                mma_fp16(acc[ma][nb*2+1], ah + ma*4, bh[1], bh[3]);
                mma_fp16(acc[ma][nb*2+0], al + ma*4, bh[0], bh[2]);
                mma_fp16(acc[ma][nb*2+1], al + ma*4, bh[1], bh[3]);
                mma_fp16(acc[ma][nb*2+0], ah + ma*4, bl[0], bl[2]);
                mma_fp16(acc[ma][nb*2+1], ah + ma*4, bl[1], bl[3]);
            }
        }
    }

    float* outp = g_mpart + ((size_t)(b * TSPL + blockIdx.x) << 14);
    const int g8 = lane >> 2;
    const int t4 = lane & 3;
    #pragma unroll
    for (int ma = 0; ma < 2; ma++) {
        int r = wm * 32 + ma * 16 + g8;
        #pragma unroll
        for (int na = 0; na < 8; na++) {
            int col = wn * 64 + na * 8 + t4 * 2;
            *(float2*)&outp[(size_t)r * D + col] =
                make_float2(acc[ma][na][0], acc[ma][na][1]);
            *(float2*)&outp[(size_t)(r + 8) * D + col] =
                make_float2(acc[ma][na][2], acc[ma][na][3]);
        }
    }
}

// ===========================================================================
// Kernel 2b: reduce partials -> M, emit fp16 hi/lo.
// ===========================================================================
__global__ __launch_bounds__(256) void reduce_m_kernel()
{
    int idx = blockIdx.x * 256 + threadIdx.x;    // 0..65535
    int b   = idx >> 14;
    int ij  = idx & 16383;
    float s = 0.0f;
    #pragma unroll
    for (int p = 0; p < TSPL; p++)
        s += g_mpart[(((size_t)(b * TSPL + p)) << 14) + ij];
    __half h = __float2half_rn(s);
    g_mh[idx] = h;
    g_ml[idx] = __float2half_rn(s - __half2float(h));
}

// ===========================================================================
// Kernel 3: out = scale * q @ M on tensor cores, 3-term fp16.
// A = qh/ql [s][d] (non-trans); B = Mh/Ml [d][e] via ldmatrix.trans.
// ===========================================================================
__global__ __launch_bounds__(256) void out_mma_kernel(float* __restrict__ out)
{
    extern __shared__ char smem[];
    const uint32_t sb = s2u(smem);
    const uint32_t sQh = sb, sQl = sb + TILE3, sMh = sb + 2*TILE3, sMl = sb + 3*TILE3;

    const int tid  = threadIdx.x;
    const int lane = tid & 31;
    const int wid  = tid >> 5;
    const int wm   = wid & 3;        // s block (32)
    const int wn   = wid >> 2;       // e block (64)
    const int b    = blockIdx.y;
    const int s0   = blockIdx.x * 128;

    const __half* qhg = g_qh + ((size_t)b * SEQ + s0) * D;
    const __half* qlg = g_ql + ((size_t)b * SEQ + s0) * D;
    const __half* mhg = g_mh + ((size_t)b << 14);
    const __half* mlg = g_ml + ((size_t)b << 14);

    #pragma unroll
    for (int i = 0; i < 8; i++) {
        int slot = tid + i * 256;
        int r = slot >> 4, u = slot & 15;
        uint32_t so = (uint32_t)(r * TS3 + u * 16);
        size_t go = (size_t)r * D + u * 8;
        cpa16(sQh + so, qhg + go);
        cpa16(sQl + so, qlg + go);
        cpa16(sMh + so, mhg + go);
        cpa16(sMl + so, mlg + go);
    }
    asm volatile("cp.async.commit_group;" ::: "memory");
    asm volatile("cp.async.wait_group 0;" ::: "memory");
    __syncthreads();

    float acc[2][8][4];
    #pragma unroll
    for (int i = 0; i < 2; i++)
        #pragma unroll
        for (int j = 0; j < 8; j++)
            #pragma unroll
            for (int q = 0; q < 4; q++) acc[i][j][q] = 0.0f;

    const uint32_t lrA  = (uint32_t)(wm * 32 + (lane & 15));
    const uint32_t lcb  = (uint32_t)((lane >> 4) << 4);
    const uint32_t trow = (uint32_t)(((lane >> 4) & 1) * 8 + (lane & 7));
    const uint32_t tcb  = (uint32_t)(((lane >> 3) & 1) * 16);

    #pragma unroll
    for (int ks = 0; ks < 8; ks++) {
        uint32_t kb = (uint32_t)(ks * 32) + lcb;
        uint32_t ah[8], al[8];
        ldsm4(ah,     sQh + lrA * TS3 + kb);
        ldsm4(ah + 4, sQh + (lrA + 16) * TS3 + kb);
        ldsm4(al,     sQl + lrA * TS3 + kb);
        ldsm4(al + 4, sQl + (lrA + 16) * TS3 + kb);
        uint32_t boff = ((uint32_t)(ks * 16) + trow) * TS3 + tcb;
        #pragma unroll
        for (int nb = 0; nb < 4; nb++) {
            uint32_t eb = (uint32_t)(wn * 128 + nb * 32);
            uint32_t bh[4], bl[4];
            ldsm4t(bh, sMh + boff + eb);
            ldsm4t(bl, sMl + boff + eb);
            #pragma unroll
            for (int ma = 0; ma < 2; ma++) {
                mma_fp16(acc[ma][nb*2+0], ah + ma*4, bh[0], bh[2]);
                mma_fp16(acc[ma][nb*2+1], ah + ma*4, bh[1], bh[3]);
                mma_fp16(acc[ma][nb*2+0], al + ma*4, bh[0], bh[2]);
                mma_fp16(acc[ma][nb*2+1], al + ma*4, bh[1], bh[3]);
                mma_fp16(acc[ma][nb*2+0], ah + ma*4, bl[0], bl[2]);
                mma_fp16(acc[ma][nb*2+1], ah + ma*4, bl[1], bl[3]);
            }
        }
    }

    const float scale = 0.08838834764831845f;    // 128^-0.5
    const int g8 = lane >> 2;
    const int t4 = lane & 3;
    #pragma unroll
    for (int ma = 0; ma < 2; ma++) {
        int r = s0 + wm * 32 + ma * 16 + g8;
        #pragma unroll
        for (int na = 0; na < 8; na++) {
            int col = wn * 64 + na * 8 + t4 * 2;
            *(float2*)&out[((size_t)b * SEQ + r) * D + col] =
                make_float2(acc[ma][na][0] * scale, acc[ma][na][1] * scale);
            *(float2*)&out[((size_t)b * SEQ + r + 8) * D + col] =
                make_float2(acc[ma][na][2] * scale, acc[ma][na][3] * scale);
        }
    }
}

// ---------------------------------------------------------------------------
extern "C" void kernel_launch(void* const* d_in, const int* in_sizes, int n_in,
                              void* d_out, int out_size)
{
    const float* x  = (const float*)d_in[0];
    const float* Wq = (const float*)d_in[1];
    const float* bq = (const float*)d_in[2];
    const float* Wk = (const float*)d_in[3];
    const float* bk = (const float*)d_in[4];
    const float* Wv = (const float*)d_in[5];
    const float* bv = (const float*)d_in[6];
    float* out = (float*)d_out;

    cudaFuncSetAttribute(qkv_mma_kernel,
                         cudaFuncAttributeMaxDynamicSharedMemorySize, 2 * STG2);
    cudaFuncSetAttribute(ktv_mma_kernel,
                         cudaFuncAttributeMaxDynamicSharedMemorySize, 4 * TILE3);
    cudaFuncSetAttribute(out_mma_kernel,
                         cudaFuncAttributeMaxDynamicSharedMemorySize, 4 * TILE3);

    cvt_kernel<<<16768, 256>>>(x, Wq, Wk, Wv);
    qkv_mma_kernel<<<dim3(ROWS / 128, 3), 256, 2 * STG2>>>(bq, bk, bv);
    ktv_mma_kernel<<<dim3(TSPL, BATCH), 256, 4 * TILE3>>>();
    reduce_m_kernel<<<256, 256>>>();
    out_mma_kernel<<<dim3(SEQ / 128, BATCH), 256, 4 * TILE3>>>(out);
}

// round 6
// speedup vs baseline: 4.1997x; 1.0680x over previous
#include <cuda_runtime.h>
#include <cuda_fp16.h>
#include <cstdint>

#define D      128
#define DM     1024
#define BATCH  4
#define SEQ    4096
#define ROWS   (BATCH * SEQ)   // 16384
#define TSPL   16              // ktv split count
#define NCH2   16              // qkv K chunks of 64

// Scratch (allocation-free rule: __device__ globals)
__device__ __half g_xh[(size_t)ROWS * DM];
__device__ __half g_wh[3 * D * DM];
__device__ __half g_qh[ROWS * D];
__device__ __half g_kh[ROWS * D];
__device__ __half g_vh[ROWS * D];
__device__ float  g_mpart[BATCH * TSPL * D * D];
__device__ __half g_mh[BATCH * D * D];
__device__ __half g_ml[BATCH * D * D];

// ===========================================================================
// helpers (sm_80-era PTX: ldmatrix / mma.sync / cp.async)
// ===========================================================================
__device__ __forceinline__ uint32_t s2u(const void* p) {
    uint32_t a;
    asm("{ .reg .u64 t; cvta.to.shared.u64 t, %1; cvt.u32.u64 %0, t; }"
        : "=r"(a) : "l"(p));
    return a;
}
__device__ __forceinline__ void ldsm4(uint32_t* r, uint32_t addr) {
    asm volatile("ldmatrix.sync.aligned.m8n8.x4.shared.b16 {%0,%1,%2,%3}, [%4];"
                 : "=r"(r[0]), "=r"(r[1]), "=r"(r[2]), "=r"(r[3]) : "r"(addr));
}
__device__ __forceinline__ void ldsm4t(uint32_t* r, uint32_t addr) {
    asm volatile("ldmatrix.sync.aligned.m8n8.x4.trans.shared.b16 {%0,%1,%2,%3}, [%4];"
                 : "=r"(r[0]), "=r"(r[1]), "=r"(r[2]), "=r"(r[3]) : "r"(addr));
}
__device__ __forceinline__ void mma_fp16(float* d, const uint32_t* a,
                                         uint32_t b0, uint32_t b1) {
    asm volatile(
        "mma.sync.aligned.m16n8k16.row.col.f32.f16.f16.f32 "
        "{%0,%1,%2,%3}, {%4,%5,%6,%7}, {%8,%9}, {%0,%1,%2,%3};"
        : "+f"(d[0]), "+f"(d[1]), "+f"(d[2]), "+f"(d[3])
        : "r"(a[0]), "r"(a[1]), "r"(a[2]), "r"(a[3]), "r"(b0), "r"(b1));
}
__device__ __forceinline__ void cpa16(uint32_t dst, const void* src) {
    asm volatile("cp.async.cg.shared.global [%0], [%1], 16;" :: "r"(dst), "l"(src));
}

// ===========================================================================
// Kernel 0: convert x -> fp16 hi; W -> fp16 hi.
// ===========================================================================
__global__ __launch_bounds__(256) void cvt_kernel(
    const float* __restrict__ x,
    const float* __restrict__ Wq, const float* __restrict__ Wk,
    const float* __restrict__ Wv)
{
    const size_t NX = (size_t)ROWS * DM;           // 16,777,216
    size_t i4 = ((size_t)blockIdx.x * 256 + threadIdx.x) * 4;

    if (i4 < NX) {
        float4 v = *(const float4*)&x[i4];
        __half2 hp0 = __halves2half2(__float2half_rn(v.x), __float2half_rn(v.y));
        __half2 hp1 = __halves2half2(__float2half_rn(v.z), __float2half_rn(v.w));
        *(__half2*)&g_xh[i4]     = hp0;
        *(__half2*)&g_xh[i4 + 2] = hp1;
    } else {
        size_t j = i4 - NX;
        if (j >= (size_t)3 * D * DM) return;
        size_t w = j >> 17;                         // which W
        const float* src = (w == 0) ? Wq : (w == 1) ? Wk : Wv;
        size_t off = j & 131071;
        float4 v = *(const float4*)&src[off];
        __half2 hp0 = __halves2half2(__float2half_rn(v.x), __float2half_rn(v.y));
        __half2 hp1 = __halves2half2(__float2half_rn(v.z), __float2half_rn(v.w));
        *(__half2*)&g_wh[j]     = hp0;
        *(__half2*)&g_wh[j + 2] = hp1;
    }
}

// ===========================================================================
// Kernel 1: QKV projection, 1-term fp16 mma.
// C[row,d] = x[row,:] . W[d,:] + b[d]; A = xh, B = Wh.
// CTA 128x128xK64 double buffered; warps 4M x 2N (warp 32x64).
// Outputs fp16 hi only.
// ===========================================================================
#define TS2   144                 // smem bytes per row (128 data + 16 pad)
#define TILE2 (128 * TS2)         // 18432
#define STG2  (2 * TILE2)         // 36864 per stage (Ah, Bh)

__global__ __launch_bounds__(256, 2) void qkv_mma_kernel(
    const float* __restrict__ bq, const float* __restrict__ bk,
    const float* __restrict__ bv)
{
    extern __shared__ char smem[];
    const uint32_t sb = s2u(smem);

    const int tid  = threadIdx.x;
    const int lane = tid & 31;
    const int wid  = tid >> 5;
    const int wm   = wid & 3;        // 32-row M block
    const int wn   = wid >> 2;       // 64-col N block
    const int head = blockIdx.y;
    const int row0 = blockIdx.x * 128;

    const __half* Ahg = g_xh + (size_t)row0 * DM;
    const __half* Bhg = g_wh + ((size_t)head << 17);
    const float* bias = (head == 0) ? bq : (head == 1) ? bk : bv;
    __half* oh = (head == 0) ? g_qh : (head == 1) ? g_kh : g_vh;

    // cp.async mapping: 128 rows x 8 16B-units = 1024 slots, 4 per thread/tile.
    int cr[4], cu[4];
    #pragma unroll
    for (int i = 0; i < 4; i++) {
        int slot = tid + i * 256;
        cr[i] = slot >> 3;
        cu[i] = slot & 7;
    }

    #define QISSUE(c) do {                                                     \
        uint32_t _b = sb + ((c) & 1) * STG2;                                   \
        _Pragma("unroll")                                                      \
        for (int _i = 0; _i < 4; _i++) {                                       \
            uint32_t _so = (uint32_t)(cr[_i] * TS2 + cu[_i] * 16);             \
            size_t _go = (size_t)cr[_i] * DM + (c) * 64 + cu[_i] * 8;          \
            cpa16(_b + _so,         Ahg + _go);                                \
            cpa16(_b + TILE2 + _so, Bhg + _go);                                \
        }                                                                      \
    } while (0)

    float acc[2][8][4];
    #pragma unroll
    for (int i = 0; i < 2; i++)
        #pragma unroll
        for (int j = 0; j < 8; j++)
            #pragma unroll
            for (int q = 0; q < 4; q++) acc[i][j][q] = 0.0f;

    QISSUE(0);
    asm volatile("cp.async.commit_group;" ::: "memory");
    QISSUE(1);
    asm volatile("cp.async.commit_group;" ::: "memory");

    const uint32_t lrA = (uint32_t)(wm * 32 + (lane & 15));
    const uint32_t lcb = (uint32_t)((lane >> 4) << 4);

    for (int c = 0; c < NCH2; c++) {
        asm volatile("cp.async.wait_group 1;" ::: "memory");
        __syncthreads();

        uint32_t base = sb + (c & 1) * STG2;
        uint32_t aH = base, bH = base + TILE2;

        #pragma unroll
        for (int ks = 0; ks < 4; ks++) {
            uint32_t kb = (uint32_t)(ks * 32) + lcb;
            uint32_t ah[8];
            ldsm4(ah,     aH + lrA * TS2 + kb);
            ldsm4(ah + 4, aH + (lrA + 16) * TS2 + kb);
            #pragma unroll
            for (int nb = 0; nb < 4; nb++) {
                uint32_t rb = (uint32_t)(wn * 64 + nb * 16 + (lane & 15));
                uint32_t bh[4];
                ldsm4(bh, bH + rb * TS2 + kb);
                #pragma unroll
                for (int ma = 0; ma < 2; ma++) {
                    mma_fp16(acc[ma][nb*2+0], ah + ma*4, bh[0], bh[2]);
                    mma_fp16(acc[ma][nb*2+1], ah + ma*4, bh[1], bh[3]);
                }
            }
        }
        __syncthreads();
        if (c + 2 < NCH2) QISSUE(c + 2);
        asm volatile("cp.async.commit_group;" ::: "memory");
    }

    // Epilogue: add bias, store fp16 hi.
    const int g8  = lane >> 2;
    const int t4  = lane & 3;
    #pragma unroll
    for (int ma = 0; ma < 2; ma++) {
        int r = row0 + wm * 32 + ma * 16 + g8;
        #pragma unroll
        for (int na = 0; na < 8; na++) {
            int col = wn * 64 + na * 8 + t4 * 2;
            float bx = __ldg(&bias[col]), by = __ldg(&bias[col + 1]);
            float v0x = acc[ma][na][0] + bx, v0y = acc[ma][na][1] + by;
            float v1x = acc[ma][na][2] + bx, v1y = acc[ma][na][3] + by;
            *(__half2*)&oh[(size_t)r * D + col] =
                __halves2half2(__float2half_rn(v0x), __float2half_rn(v0y));
            *(__half2*)&oh[(size_t)(r + 8) * D + col] =
                __halves2half2(__float2half_rn(v1x), __float2half_rn(v1y));
        }
    }
}

// ===========================================================================
// Kernel 2a: ktv partials on tensor cores, 1-term fp16.
// M_part[d,e] = sum_{t in split} kh[t,d] * vh[t,e].
// Each CTA covers 256 t-rows as 2 chunks of 128. K^T and v via ldmatrix.trans.
// ===========================================================================
#define TS3   272                 // 256 data + 16 pad
#define TILE3 (128 * TS3)         // 34816

__global__ __launch_bounds__(256) void ktv_mma_kernel()
{
    extern __shared__ char smem[];
    const uint32_t sb = s2u(smem);
    const uint32_t sKh = sb, sVh = sb + TILE3;

    const int tid  = threadIdx.x;
    const int lane = tid & 31;
    const int wid  = tid >> 5;
    const int wm   = wid & 3;        // d block (32)
    const int wn   = wid >> 2;       // e block (64)
    const int b    = blockIdx.y;
    const int t0   = blockIdx.x * 256;

    float acc[2][8][4];
    #pragma unroll
    for (int i = 0; i < 2; i++)
        #pragma unroll
        for (int j = 0; j < 8; j++)
            #pragma unroll
            for (int q = 0; q < 4; q++) acc[i][j][q] = 0.0f;

    const uint32_t trow = (uint32_t)(((lane >> 4) & 1) * 8 + (lane & 7));
    const uint32_t tcb  = (uint32_t)(((lane >> 3) & 1) * 16);

    for (int cc = 0; cc < 2; cc++) {
        const __half* khg = g_kh + ((size_t)b * SEQ + t0 + cc * 128) * D;
        const __half* vhg = g_vh + ((size_t)b * SEQ + t0 + cc * 128) * D;

        #pragma unroll
        for (int i = 0; i < 8; i++) {
            int slot = tid + i * 256;          // 2048 slots: 128 rows x 16 units
            int r = slot >> 4, u = slot & 15;
            uint32_t so = (uint32_t)(r * TS3 + u * 16);
            size_t go = (size_t)r * D + u * 8;
            cpa16(sKh + so, khg + go);
            cpa16(sVh + so, vhg + go);
        }
        asm volatile("cp.async.commit_group;" ::: "memory");
        asm volatile("cp.async.wait_group 0;" ::: "memory");
        __syncthreads();

        #pragma unroll
        for (int ks = 0; ks < 8; ks++) {
            uint32_t aoff = ((uint32_t)(ks * 16) + trow) * TS3 + tcb;
            uint32_t ah[8];
            ldsm4t(ah,     sKh + aoff + wm * 64);
            ldsm4t(ah + 4, sKh + aoff + wm * 64 + 32);
            #pragma unroll
            for (int nb = 0; nb < 4; nb++) {
                uint32_t eb = (uint32_t)(wn * 128 + nb * 32);
                uint32_t bh[4];
                ldsm4t(bh, sVh + aoff + eb);
                #pragma unroll
                for (int ma = 0; ma < 2; ma++) {
                    mma_fp16(acc[ma][nb*2+0], ah + ma*4, bh[0], bh[2]);
                    mma_fp16(acc[ma][nb*2+1], ah + ma*4, bh[1], bh[3]);
                }
            }
        }
        __syncthreads();
    }

    float* outp = g_mpart + ((size_t)(b * TSPL + blockIdx.x) << 14);
    const int g8 = lane >> 2;
    const int t4 = lane & 3;
    #pragma unroll
    for (int ma = 0; ma < 2; ma++) {
        int r = wm * 32 + ma * 16 + g8;
        #pragma unroll
        for (int na = 0; na < 8; na++) {
            int col = wn * 64 + na * 8 + t4 * 2;
            *(float2*)&outp[(size_t)r * D + col] =
                make_float2(acc[ma][na][0], acc[ma][na][1]);
            *(float2*)&outp[(size_t)(r + 8) * D + col] =
                make_float2(acc[ma][na][2], acc[ma][na][3]);
        }
    }
}

// ===========================================================================
// Kernel 2b: reduce partials -> M, emit fp16 hi/lo.
// ===========================================================================
__global__ __launch_bounds__(256) void reduce_m_kernel()
{
    int idx = blockIdx.x * 256 + threadIdx.x;    // 0..65535
    int b   = idx >> 14;
    int ij  = idx & 16383;
    float s = 0.0f;
    #pragma unroll
    for (int p = 0; p < TSPL; p++)
        s += g_mpart[(((size_t)(b * TSPL + p)) << 14) + ij];
    __half h = __float2half_rn(s);
    g_mh[idx] = h;
    g_ml[idx] = __float2half_rn(s - __half2float(h));
}

// ===========================================================================
// Kernel 3: out = scale * q @ M on tensor cores, 2-term (qh*Mh + qh*Ml).
// A = qh [s][d] (non-trans); B = Mh/Ml [d][e] via ldmatrix.trans.
// ===========================================================================
__global__ __launch_bounds__(256) void out_mma_kernel(float* __restrict__ out)
{
    extern __shared__ char smem[];
    const uint32_t sb = s2u(smem);
    const uint32_t sQh = sb, sMh = sb + TILE3, sMl = sb + 2*TILE3;

    const int tid  = threadIdx.x;
    const int lane = tid & 31;
    const int wid  = tid >> 5;
    const int wm   = wid & 3;        // s block (32)
    const int wn   = wid >> 2;       // e block (64)
    const int b    = blockIdx.y;
    const int s0   = blockIdx.x * 128;

    const __half* qhg = g_qh + ((size_t)b * SEQ + s0) * D;
    const __half* mhg = g_mh + ((size_t)b << 14);
    const __half* mlg = g_ml + ((size_t)b << 14);

    #pragma unroll
    for (int i = 0; i < 8; i++) {
        int slot = tid + i * 256;
        int r = slot >> 4, u = slot & 15;
        uint32_t so = (uint32_t)(r * TS3 + u * 16);
        size_t go = (size_t)r * D + u * 8;
        cpa16(sQh + so, qhg + go);
        cpa16(sMh + so, mhg + go);
        cpa16(sMl + so, mlg + go);
    }
    asm volatile("cp.async.commit_group;" ::: "memory");
    asm volatile("cp.async.wait_group 0;" ::: "memory");
    __syncthreads();

    float acc[2][8][4];
    #pragma unroll
    for (int i = 0; i < 2; i++)
        #pragma unroll
        for (int j = 0; j < 8; j++)
            #pragma unroll
            for (int q = 0; q < 4; q++) acc[i][j][q] = 0.0f;

    const uint32_t lrA  = (uint32_t)(wm * 32 + (lane & 15));
    const uint32_t lcb  = (uint32_t)((lane >> 4) << 4);
    const uint32_t trow = (uint32_t)(((lane >> 4) & 1) * 8 + (lane & 7));
    const uint32_t tcb  = (uint32_t)(((lane >> 3) & 1) * 16);

    #pragma unroll
    for (int ks = 0; ks < 8; ks++) {
        uint32_t kb = (uint32_t)(ks * 32) + lcb;
        uint32_t ah[8];
        ldsm4(ah,     sQh + lrA * TS3 + kb);
        ldsm4(ah + 4, sQh + (lrA + 16) * TS3 + kb);
        uint32_t boff = ((uint32_t)(ks * 16) + trow) * TS3 + tcb;
        #pragma unroll
        for (int nb = 0; nb < 4; nb++) {
            uint32_t eb = (uint32_t)(wn * 128 + nb * 32);
            uint32_t bh[4], bl[4];
            ldsm4t(bh, sMh + boff + eb);
            ldsm4t(bl, sMl + boff + eb);
            #pragma unroll
            for (int ma = 0; ma < 2; ma++) {
                mma_fp16(acc[ma][nb*2+0], ah + ma*4, bh[0], bh[2]);
                mma_fp16(acc[ma][nb*2+1], ah + ma*4, bh[1], bh[3]);
                mma_fp16(acc[ma][nb*2+0], ah + ma*4, bl[0], bl[2]);
                mma_fp16(acc[ma][nb*2+1], ah + ma*4, bl[1], bl[3]);
            }
        }
    }

    const float scale = 0.08838834764831845f;    // 128^-0.5
    const int g8 = lane >> 2;
    const int t4 = lane & 3;
    #pragma unroll
    for (int ma = 0; ma < 2; ma++) {
        int r = s0 + wm * 32 + ma * 16 + g8;
        #pragma unroll
        for (int na = 0; na < 8; na++) {
            int col = wn * 64 + na * 8 + t4 * 2;
            *(float2*)&out[((size_t)b * SEQ + r) * D + col] =
                make_float2(acc[ma][na][0] * scale, acc[ma][na][1] * scale);
            *(float2*)&out[((size_t)b * SEQ + r + 8) * D + col] =
                make_float2(acc[ma][na][2] * scale, acc[ma][na][3] * scale);
        }
    }
}

// ---------------------------------------------------------------------------
extern "C" void kernel_launch(void* const* d_in, const int* in_sizes, int n_in,
                              void* d_out, int out_size)
{
    const float* x  = (const float*)d_in[0];
    const float* Wq = (const float*)d_in[1];
    const float* bq = (const float*)d_in[2];
    const float* Wk = (const float*)d_in[3];
    const float* bk = (const float*)d_in[4];
    const float* Wv = (const float*)d_in[5];
    const float* bv = (const float*)d_in[6];
    float* out = (float*)d_out;

    cudaFuncSetAttribute(qkv_mma_kernel,
                         cudaFuncAttributeMaxDynamicSharedMemorySize, 2 * STG2);
    cudaFuncSetAttribute(ktv_mma_kernel,
                         cudaFuncAttributeMaxDynamicSharedMemorySize, 2 * TILE3);
    cudaFuncSetAttribute(out_mma_kernel,
                         cudaFuncAttributeMaxDynamicSharedMemorySize, 3 * TILE3);

    cvt_kernel<<<16768, 256>>>(x, Wq, Wk, Wv);
    qkv_mma_kernel<<<dim3(ROWS / 128, 3), 256, 2 * STG2>>>(bq, bk, bv);
    ktv_mma_kernel<<<dim3(TSPL, BATCH), 256, 2 * TILE3>>>();
    reduce_m_kernel<<<256, 256>>>();
    out_mma_kernel<<<dim3(SEQ / 128, BATCH), 256, 3 * TILE3>>>(out);
}